// round 9
// baseline (speedup 1.0000x reference)
#include <cuda_runtime.h>
#include <math.h>

#define T_STEPS 400
#define BATCH   128
#define HID     512
#define OC      64
#define NSPLIT  8
#define K1S     72     // 576/8
#define K2S     128    // 1024/8

typedef unsigned long long ull;

// ---------------- device scratch ----------------
__device__ __align__(16) float g_ybuf[OC * T_STEPS * BATCH];   // [oc][t][b]
__device__ __align__(16) float g_seq [T_STEPS * OC * BATCH];   // [t][c][b]
__device__ float g_scale[OC];
__device__ float g_shift[OC];
__device__ __align__(16) float g_memL[OC * BATCH];
__device__ __align__(16) float g_S1[576 * BATCH];     // rows 0-63 spikes, 64-575 mem1
__device__ __align__(16) float g_S2[1024 * BATCH];    // rows 0-511 spk1, 512-1023 mem2
__device__ __align__(16) float g_syn1[HID * BATCH];
__device__ __align__(16) float g_syn2[HID * BATCH];
__device__ __align__(16) float g_acc2[HID * BATCH];
__device__ __align__(16) float g_partA[NSPLIT * 2048 * BATCH];  // gemm1 partials
__device__ __align__(16) float g_partB[NSPLIT * 2048 * BATCH];  // gemm2 partials
__device__ unsigned g_flags[128];   // per-CTA barrier flags (monotonic)

// ---------------- helpers ----------------
__device__ __forceinline__ float sigf(float x) { return 1.f / (1.f + expf(-x)); }
__device__ __forceinline__ ull packf2(float w) {
    ull r; unsigned u = __float_as_uint(w);
    asm("mov.b64 %0, {%1, %1};" : "=l"(r) : "r"(u));
    return r;
}
__device__ __forceinline__ void fma2(ull& acc, ull a, ull b) {
    asm("fma.rn.f32x2 %0, %1, %2, %0;" : "+l"(acc) : "l"(a), "l"(b));
}
__device__ __forceinline__ void cpa16cg(void* dst_smem, const void* src) {
    unsigned d = (unsigned)__cvta_generic_to_shared(dst_smem);
    asm volatile("cp.async.cg.shared.global [%0], [%1], 16;" :: "r"(d), "l"(src));
}
#define CP_COMMIT() asm volatile("cp.async.commit_group;" ::: "memory")

// single-level flag barrier: each CTA posts its own slot with release, then
// all CTAs poll all 128 flags directly (threads 0-127, one flag each).
// Monotonic phases survive graph replays (base re-read from own flag).
__device__ __forceinline__ void grid_barrier(unsigned ph) {
    __syncthreads();
    if (threadIdx.x == 0)
        asm volatile("st.release.gpu.u32 [%0], %1;"
                     :: "l"(g_flags + blockIdx.x), "r"(ph) : "memory");
    if (threadIdx.x < 128) {
        unsigned v;
        do {
            asm volatile("ld.acquire.gpu.u32 %0, [%1];"
                         : "=r"(v) : "l"(g_flags + threadIdx.x));
        } while ((int)(v - ph) < 0);
    }
    __syncthreads();
}

// ---------------- conv1d (pad=2, k=5): block=t, threads=b ----------------
__global__ void conv_kernel(const float* __restrict__ x, const float* __restrict__ w) {
    __shared__ float s_w[OC * 70];
    int t = blockIdx.x, b = threadIdx.x;
    for (int i = b; i < OC * 70; i += 128) s_w[i] = w[i];
    float xr[5][14];
#pragma unroll
    for (int k = 0; k < 5; k++) {
        int tt = t + k - 2;
        bool ok = (tt >= 0 && tt < T_STEPS);
#pragma unroll
        for (int c = 0; c < 14; c++)
            xr[k][c] = ok ? x[(tt * BATCH + b) * 14 + c] : 0.f;
    }
    __syncthreads();
    for (int oc = 0; oc < OC; oc++) {
        float acc = 0.f;
        const float* wr = s_w + oc * 70;
#pragma unroll
        for (int c = 0; c < 14; c++)
#pragma unroll
            for (int k = 0; k < 5; k++)
                acc = fmaf(xr[k][c], wr[c * 5 + k], acc);
        g_ybuf[oc * (T_STEPS * BATCH) + t * BATCH + b] = acc;
    }
}

__global__ void stats_kernel(const float* __restrict__ bn_g, const float* __restrict__ bn_b) {
    int c = blockIdx.x;
    const float* base = g_ybuf + c * (T_STEPS * BATCH);
    double s = 0.0, sq = 0.0;
    for (int i = threadIdx.x; i < T_STEPS * BATCH; i += 256) {
        float v = base[i];
        s += v; sq += (double)v * (double)v;
    }
    __shared__ double rs[256], rq[256];
    rs[threadIdx.x] = s; rq[threadIdx.x] = sq;
    __syncthreads();
    for (int st = 128; st > 0; st >>= 1) {
        if (threadIdx.x < st) { rs[threadIdx.x] += rs[threadIdx.x + st]; rq[threadIdx.x] += rq[threadIdx.x + st]; }
        __syncthreads();
    }
    if (threadIdx.x == 0) {
        double n = (double)(T_STEPS * BATCH);
        double mu = rs[0] / n;
        double var = rq[0] / n - mu * mu;
        float sc = bn_g[c] * (float)(1.0 / sqrt(var + 1e-5));
        g_scale[c] = sc;
        g_shift[c] = bn_b[c] - (float)mu * sc;
    }
}

__global__ void norm_kernel() {
    int i = blockIdx.x * 256 + threadIdx.x;
    if (i >= OC * T_STEPS * BATCH) return;
    int oc = i / (T_STEPS * BATCH);
    int rem = i % (T_STEPS * BATCH);
    int t = rem / BATCH, b = rem % BATCH;
    g_seq[t * (OC * BATCH) + oc * BATCH + b] = g_ybuf[i] * g_scale[oc] + g_shift[oc];
}

// ---------------- persistent scan kernel ----------------
// grid 128 = 16 gate-tiles(128 rows) x 8 k-splits; 512 threads
// warp owns 8 gate rows (broadcast non-dup f32 weights), lane owns 4 batch
// smem: w1 [72][128] f32 + w2 [128][128] f32 + state ring 4 x 1024 f32

template <int KSPLIT>
__device__ __forceinline__ void gemm_phase(const float* __restrict__ gstate,
                                           const float* __restrict__ wsm,
                                           float* __restrict__ spart,
                                           float* __restrict__ sbuf,
                                           int warp, int lane)
{
    const int NCHK = KSPLIT / 8;      // chunk = 8 k rows = 1024 floats = 4KB
    const int tid = threadIdx.x;

    auto fetch = [&](int c) {
        if (c < NCHK && tid < 256)
            cpa16cg(sbuf + ((c & 3) << 10) + tid * 4, gstate + (c << 10) + tid * 4);
        CP_COMMIT();
    };
    fetch(0); fetch(1); fetch(2);

    ull acc[8][2];
#pragma unroll
    for (int j = 0; j < 8; j++) { acc[j][0] = 0ull; acc[j][1] = 0ull; }

    for (int c = 0; c < NCHK; c++) {
        asm volatile("cp.async.wait_group 2;" ::: "memory");
        __syncthreads();
        fetch(c + 3);
        const float* sb = sbuf + ((c & 3) << 10) + lane * 4;
        const float* wb = wsm + (c << 10) + warp * 8;
#pragma unroll
        for (int kk = 0; kk < 8; kk++) {
            ulonglong2 sv = *(const ulonglong2*)(sb + (kk << 7));
            float4 wA = *(const float4*)(wb + (kk << 7));
            float4 wB = *(const float4*)(wb + (kk << 7) + 4);
            ull w0 = packf2(wA.x), w1 = packf2(wA.y), w2 = packf2(wA.z), w3 = packf2(wA.w);
            ull w4 = packf2(wB.x), w5 = packf2(wB.y), w6 = packf2(wB.z), w7 = packf2(wB.w);
            fma2(acc[0][0], sv.x, w0); fma2(acc[0][1], sv.y, w0);
            fma2(acc[1][0], sv.x, w1); fma2(acc[1][1], sv.y, w1);
            fma2(acc[2][0], sv.x, w2); fma2(acc[2][1], sv.y, w2);
            fma2(acc[3][0], sv.x, w3); fma2(acc[3][1], sv.y, w3);
            fma2(acc[4][0], sv.x, w4); fma2(acc[4][1], sv.y, w4);
            fma2(acc[5][0], sv.x, w5); fma2(acc[5][1], sv.y, w5);
            fma2(acc[6][0], sv.x, w6); fma2(acc[6][1], sv.y, w6);
            fma2(acc[7][0], sv.x, w7); fma2(acc[7][1], sv.y, w7);
        }
    }

    // write partials: rows warp*8+j, cols lane*4..+4
#pragma unroll
    for (int j = 0; j < 8; j++) {
        ulonglong2 v; v.x = acc[j][0]; v.y = acc[j][1];
        *(ulonglong2*)(spart + (warp * 8 + j) * 128 + lane * 4) = v;
    }
}

__device__ __forceinline__ void epi_slstm(int layer, float thr,
                                          const float* __restrict__ part,
                                          const float* __restrict__ bi,
                                          const float* __restrict__ bh) {
    int e = blockIdx.x * 512 + threadIdx.x;   // [0, 65536)
    int h = e >> 7, b = e & 127;
    float sums[4];
#pragma unroll
    for (int gt = 0; gt < 4; gt++) {
        int r = gt * 512 + h;
        const float* pp = part + (r >> 7) * 16384 + (r & 127) * 128 + b;
        float s = 0.f;
#pragma unroll
        for (int sp = 0; sp < NSPLIT; sp++)
            s += __ldcg(pp + sp * (2048 * 128));
        sums[gt] = s + __ldg(bi + r) + __ldg(bh + r);
    }
    float* syn  = (layer == 1) ? g_syn1 : g_syn2;
    float* memr = (layer == 1) ? (g_S1 + 64 * 128) : (g_S2 + 512 * 128);
    float sv = syn[e];
    float mo = memr[e];
    float reset = (mo > thr) ? thr : 0.f;
    float sn = sigf(sums[1]) * sv + sigf(sums[0]) * tanhf(sums[2]);
    float mn = sigf(sums[3]) * tanhf(sn) - reset;
    syn[e] = sn;
    memr[e] = mn;
    if (layer == 1) g_S2[e] = (mn > thr) ? 1.f : 0.f;
    else g_acc2[e] += mn;
}

__device__ __forceinline__ void lif_phase(int t, float thrL) {
    if (threadIdx.x < 64) {
        int e = blockIdx.x * 64 + threadIdx.x;
        float mo = g_memL[e];
        float xt = g_seq[t * 8192 + e];
        float reset = (mo > thrL) ? thrL : 0.f;
        float mn = 0.9f * mo + xt - reset;
        g_memL[e] = mn;
        g_S1[e] = (mn > thrL) ? 1.f : 0.f;
    }
}

__global__ void __launch_bounds__(512, 1) scan_kernel(
    const float* __restrict__ w_ih1, const float* __restrict__ w_hh1,
    const float* __restrict__ b_ih1, const float* __restrict__ b_hh1,
    const float* __restrict__ w_ih2, const float* __restrict__ w_hh2,
    const float* __restrict__ b_ih2, const float* __restrict__ b_hh2,
    const float* __restrict__ thrL_p, const float* __restrict__ thr1_p,
    const float* __restrict__ thr2_p)
{
    extern __shared__ char smem[];
    float* w1sm = (float*)smem;                 // 72*128 f32  = 36864 B
    float* w2sm = (float*)(smem + 36864);       // 128*128 f32 = 65536 B
    float* sbuf = (float*)(smem + 102400);      // 4 x 1024 f32 = 16384 B

    const int tid = threadIdx.x;
    const int cta = blockIdx.x;
    const int tile = cta >> 3, split = cta & 7;     // 16 tiles x 8 splits
    const int warp = tid >> 5, lane = tid & 31;
    const float thrL = __ldg(thrL_p), thr1 = __ldg(thr1_p), thr2 = __ldg(thr2_p);
    const int gid = cta * 512 + tid;

    // phase base: this CTA's own flag (stable — only this CTA writes it)
    unsigned ph;
    asm volatile("ld.relaxed.gpu.u32 %0, [%1];" : "=r"(ph) : "l"(g_flags + cta));

    // ---- prologue: zero recurrent state (each launch) ----
    {
        int i = gid;                       // exactly 65536 threads
        g_S1[8192 + i] = 0.f;              // mem1
        g_S2[65536 + i] = 0.f;             // mem2
        g_syn1[i] = 0.f; g_syn2[i] = 0.f; g_acc2[i] = 0.f;
    }

    // ---- prologue: pack weights (non-dup f32) into resident smem [k][gate] ----
    for (int i = tid; i < K1S * 128; i += 512) {
        int kl = i >> 7, g = i & 127;
        int r = tile * 128 + g;
        int kg = split * K1S + kl;
        w1sm[i] = (kg < 64) ? __ldg(w_ih1 + r * 64 + kg) : __ldg(w_hh1 + r * 512 + kg - 64);
    }
    for (int i = tid; i < K2S * 128; i += 512) {
        int kl = i >> 7, g = i & 127;
        int r = tile * 128 + g;
        int kg = split * K2S + kl;
        w2sm[i] = (kg < 512) ? __ldg(w_ih2 + r * 512 + kg) : __ldg(w_hh2 + r * 512 + kg - 512);
    }

    // LIF at t=0: mem starts at 0, so mem_new = x_t exactly
    if (tid < 64) {
        int e = cta * 64 + tid;
        float xt = g_seq[e];
        g_memL[e] = xt;
        g_S1[e] = (xt > thrL) ? 1.f : 0.f;
    }
    ph++; grid_barrier(ph);

    float* spartA = g_partA + split * 262144 + tile * 16384;
    float* spartB = g_partB + split * 262144 + tile * 16384;

    for (int t = 0; t < T_STEPS; t++) {
        gemm_phase<K1S>(g_S1 + split * (K1S * 128), w1sm, spartA, sbuf, warp, lane);
        ph++; grid_barrier(ph);
        epi_slstm(1, thr1, g_partA, b_ih1, b_hh1);
        if (t + 1 < T_STEPS) lif_phase(t + 1, thrL);
        ph++; grid_barrier(ph);
        gemm_phase<K2S>(g_S2 + split * (K2S * 128), w2sm, spartB, sbuf, warp, lane);
        ph++; grid_barrier(ph);
        epi_slstm(2, thr2, g_partB, b_ih2, b_hh2);
        // no 4th barrier: ping-pong partials; epi2's mem2 writes are ordered
        // before next gemm2 by the two intervening barriers.
    }
}

// ---------------- heads ----------------
__global__ void heads_kernel(const float* __restrict__ wg, const float* __restrict__ bg,
                             const float* __restrict__ wd1, const float* __restrict__ bd1,
                             const float* __restrict__ wd2, const float* __restrict__ bd2,
                             const float* __restrict__ thr_dom_p, float* __restrict__ out)
{
    __shared__ float feat[512];
    __shared__ float sd[64];
    int b = blockIdx.x, tid = threadIdx.x;
    const float thr = *thr_dom_p;
#pragma unroll
    for (int j = 0; j < 4; j++)
        feat[tid + j * 128] = g_acc2[(tid + j * 128) * 128 + b] * (1.f / 400.f);
    __syncthreads();
    if (tid < 8) {
        float acc = bg[tid];
        for (int h = 0; h < 512; h++) acc = fmaf(feat[h], wg[tid * 512 + h], acc);
        out[b * 8 + tid] = acc;
    }
    if (tid < 64) {
        float acc = bd1[tid];
        for (int h = 0; h < 512; h++) acc = fmaf(feat[h], wd1[tid * 512 + h], acc);
        sd[tid] = (acc - thr > 0.f) ? 1.f : 0.f;
    }
    __syncthreads();
    if (tid < 10) {
        float acc = bd2[tid];
        for (int k = 0; k < 64; k++) acc = fmaf(sd[k], wd2[tid * 64 + k], acc);
        out[128 * 8 + b * 10 + tid] = acc;
    }
}

extern "C" void kernel_launch(void* const* d_in, const int* in_sizes, int n_in,
                              void* d_out, int out_size) {
    const float* x       = (const float*)d_in[0];
    const float* conv_w  = (const float*)d_in[1];
    const float* bn_g    = (const float*)d_in[2];
    const float* bn_b    = (const float*)d_in[3];
    const float* w_ih1   = (const float*)d_in[4];
    const float* w_hh1   = (const float*)d_in[5];
    const float* b_ih1   = (const float*)d_in[6];
    const float* b_hh1   = (const float*)d_in[7];
    const float* w_ih2   = (const float*)d_in[8];
    const float* w_hh2   = (const float*)d_in[9];
    const float* b_ih2   = (const float*)d_in[10];
    const float* b_hh2   = (const float*)d_in[11];
    const float* wg      = (const float*)d_in[12];
    const float* bg      = (const float*)d_in[13];
    const float* wd1     = (const float*)d_in[14];
    const float* bd1     = (const float*)d_in[15];
    const float* wd2     = (const float*)d_in[16];
    const float* bd2     = (const float*)d_in[17];
    const float* thrL    = (const float*)d_in[18];
    const float* thr1    = (const float*)d_in[19];
    const float* thr2    = (const float*)d_in[20];
    const float* thrD    = (const float*)d_in[21];

    const int SMEM_SCAN = 36864 + 65536 + 16384;   // 118784 B
    cudaFuncSetAttribute(scan_kernel, cudaFuncAttributeMaxDynamicSharedMemorySize, SMEM_SCAN);

    conv_kernel<<<T_STEPS, 128>>>(x, conv_w);
    stats_kernel<<<OC, 256>>>(bn_g, bn_b);
    norm_kernel<<<(OC * T_STEPS * BATCH + 255) / 256, 256>>>();
    scan_kernel<<<128, 512, SMEM_SCAN>>>(w_ih1, w_hh1, b_ih1, b_hh1,
                                         w_ih2, w_hh2, b_ih2, b_hh2,
                                         thrL, thr1, thr2);
    heads_kernel<<<128, 128>>>(wg, bg, wd1, bd1, wd2, bd2, thrD, (float*)d_out);
}